// round 9
// baseline (speedup 1.0000x reference)
#include <cuda_runtime.h>
#include <math.h>

#define NQ 14
#define NSTATE (1 << NQ)          // 16384 amplitudes
#define THREADS 512
#define NWARP (THREADS / 32)
#define NPASS 6

struct SmallSmem {
    float2 u[NQ][2];              // per-qubit initial 2-vectors (RY embed * layer0 RX on |0>)
    float2 Tlow[64];              // product table, qubits 0..5
    float2 Thigh[256];            // product table, qubits 6..13
    float wc[2][NQ];              // cos(w/2) for layers 1,2
    float ws[2][NQ];              // sin(w/2) for layers 1,2
    unsigned dmask[2][NQ];        // columns of M_l^{-1} (pair offsets), l=1,2
    unsigned mmask[2][NQ];        // rows of M_l (parity masks), l=1,2
    unsigned ro[NQ];              // rows of M_3 (readout Z-sign masks)
    unsigned basisT[NPASS][10];   // per-pass coset-representative basis vectors
    unsigned rocode[NQ];          // 4-bit Walsh combo code per readout qubit (last pass)
    float red[NWARP][NQ];         // per-warp reduction buffer
};

__device__ __forceinline__ float2 cmulf(float2 a, float2 b) {
    return make_float2(a.x * b.x - a.y * b.y, a.x * b.y + a.y * b.x);
}

__host__ __device__ constexpr int ctzc(int k) {
    return (k & 1) ? 0 : (k & 2) ? 1 : (k & 4) ? 2 : (k & 8) ? 3 : 4;
}

// One fused multi-qubit RX pass over the whole state.
// Group G of layer L covers qubits {G + 3r : r < NGQ}; NM = 2^NGQ members per
// group; KG groups per thread (NM*KG == 32 always). Addresses are generated by
// a Gray-code XOR walk over the group's pair-offset masks d[].
template<int L, int G, int NGQ, int KG, bool FIRST, bool LAST>
__device__ __forceinline__ void do_pass(float2* __restrict__ S, SmallSmem& sm,
                                        int tid, float* acc)
{
    constexpr int PI = L * 3 + G;
    constexpr int NM = 1 << NGQ;

    unsigned d[NGQ];
    float cs[NGQ], sn[NGQ];
#pragma unroll
    for (int r = 0; r < NGQ; r++) {
        int q = G + 3 * r;
        d[r]  = sm.dmask[L][q];
        cs[r] = sm.wc[L][q];
        sn[r] = sm.ws[L][q];
    }

    // coset-representative base address (GF(2)-linear in tid)
    unsigned pb0 = 0;
#pragma unroll
    for (int j = 0; j < 9; j++)
        if ((tid >> j) & 1) pb0 ^= sm.basisT[PI][j];
    const unsigned kb0 = (KG > 1) ? sm.basisT[PI][9] : 0u;

    __syncthreads();   // previous pass stores -> this pass loads

    if constexpr (!LAST) {
        float2 A[KG][NM];
        // batched loads, Gray-order address walk (max MLP)
#pragma unroll
        for (int kg = 0; kg < KG; kg++) {
            unsigned addr = kg ? (pb0 ^ kb0) : pb0;
#pragma unroll
            for (int k = 0; k < NM; k++) {
                if (k) addr ^= d[ctzc(k)];
                const int gi = k ^ (k >> 1);
                if (FIRST)
                    A[kg][gi] = cmulf(sm.Tlow[addr & 63], sm.Thigh[addr >> 6]);
                else
                    A[kg][gi] = S[addr];
            }
        }
        // NGQ levels of RX butterflies: RX = [[c,-is],[-is,c]]
#pragma unroll
        for (int r = 0; r < NGQ; r++) {
            const float c = cs[r], s = sn[r];
#pragma unroll
            for (int kg = 0; kg < KG; kg++) {
#pragma unroll
                for (int i = 0; i < NM; i++) {
                    if (i & (1 << r)) continue;
                    const int j = i | (1 << r);
                    float2 a = A[kg][i], b = A[kg][j];
                    A[kg][i].x = c * a.x + s * b.y;  A[kg][i].y = c * a.y - s * b.x;
                    A[kg][j].x = s * a.y + c * b.x;  A[kg][j].y = -s * a.x + c * b.y;
                }
            }
        }
        // stores, same walk
#pragma unroll
        for (int kg = 0; kg < KG; kg++) {
            unsigned addr = kg ? (pb0 ^ kb0) : pb0;
#pragma unroll
            for (int k = 0; k < NM; k++) {
                if (k) addr ^= d[ctzc(k)];
                S[addr] = A[kg][k ^ (k >> 1)];
            }
        }
    } else {
        // final pass: sequential groups (register pressure), fold readout,
        // no store of the state (nothing reads it afterwards).
#pragma unroll 1
        for (int kg = 0; kg < KG; kg++) {
            const unsigned pb = kg ? (pb0 ^ kb0) : pb0;
            float2 A[NM];
            {
                unsigned addr = pb;
#pragma unroll
                for (int k = 0; k < NM; k++) {
                    if (k) addr ^= d[ctzc(k)];
                    A[k ^ (k >> 1)] = S[addr];
                }
            }
#pragma unroll
            for (int r = 0; r < NGQ; r++) {
                const float c = cs[r], s = sn[r];
#pragma unroll
                for (int i = 0; i < NM; i++) {
                    if (i & (1 << r)) continue;
                    const int j = i | (1 << r);
                    float2 a = A[i], b = A[j];
                    A[i].x = c * a.x + s * b.y;  A[i].y = c * a.y - s * b.x;
                    A[j].x = s * a.y + c * b.x;  A[j].y = -s * a.x + c * b.y;
                }
            }
            // probabilities + Walsh transform over the group
            float pr[NM];
#pragma unroll
            for (int i = 0; i < NM; i++) pr[i] = A[i].x * A[i].x + A[i].y * A[i].y;
#pragma unroll
            for (int r = 0; r < NGQ; r++) {
#pragma unroll
                for (int i = 0; i < NM; i++) {
                    if (i & (1 << r)) continue;
                    const int j = i | (1 << r);
                    float u2 = pr[i], v2 = pr[j];
                    pr[i] = u2 + v2; pr[j] = u2 - v2;
                }
            }
            // per-qubit: pick Walsh coefficient by 4-bit code, sign by parity(ro&pb)
#pragma unroll
            for (int q = 0; q < NQ; q++) {
                const unsigned code = sm.rocode[q];
                float t8[8];
#pragma unroll
                for (int j = 0; j < 8; j++) t8[j] = (code & 1) ? pr[2 * j + 1] : pr[2 * j];
                float t4[4];
#pragma unroll
                for (int j = 0; j < 4; j++) t4[j] = (code & 2) ? t8[2 * j + 1] : t8[2 * j];
                float t2[2];
#pragma unroll
                for (int j = 0; j < 2; j++) t2[j] = (code & 4) ? t4[2 * j + 1] : t4[2 * j];
                float v = (code & 8) ? t2[1] : t2[0];
                unsigned sgn = (unsigned)(__popc(sm.ro[q] & pb) & 1) << 31;
                acc[q] += __uint_as_float(__float_as_uint(v) ^ sgn);
            }
        }
    }
}

__global__ __launch_bounds__(THREADS, 1)
void qsim_kernel(const float* __restrict__ xin,
                 const float* __restrict__ win,
                 float* __restrict__ out)
{
    extern __shared__ float2 S[];           // 16384 complex amplitudes (131072 B)
    __shared__ SmallSmem sm;

    const int tid = threadIdx.x;
    const int samp = blockIdx.x;

    // ---------------- setup stage 1 ----------------
    if (tid < NQ) {
        float th = tanhf(xin[samp * NQ + tid]) * 1.57079632679489662f; // tanh(x)*pi/2
        float c, s;
        sincosf(th, &s, &c);
        float hw = win[tid] * 0.5f;
        float sw, cw;
        sincosf(hw, &sw, &cw);
        sm.u[tid][0] = make_float2(cw * c, -sw * s);
        sm.u[tid][1] = make_float2(cw * s, -sw * c);
    }
    if (tid >= 64 && tid < 64 + 2 * NQ) {
        int l = (tid - 64) / NQ, q = (tid - 64) % NQ;
        float hw = win[(l + 1) * NQ + q] * 0.5f;
        float sw, cw;
        sincosf(hw, &sw, &cw);
        sm.wc[l][q] = cw;
        sm.ws[l][q] = sw;
    }
    // GF(2) bookkeeping for the CNOT rings: M_l = L^l rows, M_l^{-1} columns
    if (tid == 0) {
        unsigned row[NQ], col[NQ];
        for (int q = 0; q < NQ; q++) { row[q] = 1u << q; col[q] = 1u << q; }
        for (int step = 1; step <= 3; ++step) {
            unsigned nr[NQ], nc[NQ];
            unsigned all = 0;
            for (int q = 0; q < NQ; q++) all ^= row[q];
            nr[0] = all ^ row[0];
            unsigned pref = row[0];
            for (int k = 1; k < NQ; k++) { pref ^= row[k]; nr[k] = pref; }
            nc[0] = col[0] ^ col[1];
            for (int q = 1; q < NQ - 1; q++) nc[q] = col[q] ^ col[q + 1];
            nc[NQ - 1] = col[0] ^ col[1] ^ col[NQ - 1];
            for (int q = 0; q < NQ; q++) { row[q] = nr[q]; col[q] = nc[q]; }
            if (step < 3) {
                for (int q = 0; q < NQ; q++) {
                    sm.dmask[step - 1][q] = col[q];
                    sm.mmask[step - 1][q] = row[q];
                }
            } else {
                for (int q = 0; q < NQ; q++) sm.ro[q] = row[q];
            }
        }
    }
    __syncthreads();

    // ---------------- setup stage 2: basis tables, readout codes, product tables ----
    if (tid < NPASS) {
        const int l = tid / 3, g = tid % 3;
        const int ng = (g < 2) ? 5 : 4;
        unsigned d[5], m[5];
        for (int r = 0; r < ng; r++) {
            int q = g + 3 * r;
            d[r] = sm.dmask[l][q];
            m[r] = sm.mmask[l][q];
        }
        // pivots via Gaussian elimination (d's are linearly independent)
        unsigned red[5]; int piv[5];
        unsigned pivmask = 0;
        for (int r = 0; r < ng; r++) {
            unsigned v = d[r];
            for (int h = 0; h < r; h++)
                if ((v >> piv[h]) & 1u) v ^= red[h];
            piv[r] = __ffs((int)v) - 1;
            red[r] = v;
            pivmask |= 1u << piv[r];
        }
        // basis of the t -> p_base linear map (non-pivot index bits, low to high)
        int idx = 0;
        for (int b = 0; b < NQ; b++) {
            if ((pivmask >> b) & 1u) continue;
            unsigned p = 1u << b;
            for (int r = 0; r < ng; r++)
                if ((m[r] >> b) & 1u) p ^= d[r];
            sm.basisT[tid][idx++] = p;
        }
    }
    if (tid == 6) {
        // readout codes for the final pass (l=1, g=2, qubits {2,5,8,11})
        for (int q = 0; q < NQ; q++) {
            unsigned c = 0;
            for (int r = 0; r < 4; r++)
                c |= (unsigned)(__popc(sm.ro[q] & sm.dmask[1][2 + 3 * r]) & 1) << r;
            sm.rocode[q] = c;
        }
    }
    if (tid < 64) {
        float2 v = sm.u[0][tid & 1];
#pragma unroll
        for (int q = 1; q < 6; q++) v = cmulf(v, sm.u[q][(tid >> q) & 1]);
        sm.Tlow[tid] = v;
    }
    if (tid >= 128 && tid < 384) {
        int t = tid - 128;
        float2 v = sm.u[6][t & 1];
#pragma unroll
        for (int q = 1; q < 8; q++) v = cmulf(v, sm.u[6 + q][(t >> q) & 1]);
        sm.Thigh[t] = v;
    }
    __syncthreads();

    float acc[NQ];
#pragma unroll
    for (int q = 0; q < NQ; q++) acc[q] = 0.0f;

    // ---------------- 6 fused passes (layer 1, layer 2) ----------------
    do_pass<0, 0, 5, 1, true,  false>(S, sm, tid, acc);
    do_pass<0, 1, 5, 1, false, false>(S, sm, tid, acc);
    do_pass<0, 2, 4, 2, false, false>(S, sm, tid, acc);
    do_pass<1, 0, 5, 1, false, false>(S, sm, tid, acc);
    do_pass<1, 1, 5, 1, false, false>(S, sm, tid, acc);
    do_pass<1, 2, 4, 2, false, true >(S, sm, tid, acc);

    // ---------------- block reduction of <Z_q> ----------------
#pragma unroll
    for (int q = 0; q < NQ; q++) {
#pragma unroll
        for (int off = 16; off; off >>= 1)
            acc[q] += __shfl_xor_sync(0xffffffffu, acc[q], off);
    }
    const int wid = tid >> 5, lane = tid & 31;
    if (lane == 0) {
#pragma unroll
        for (int q = 0; q < NQ; q++) sm.red[wid][q] = acc[q];
    }
    __syncthreads();
    if (tid < NQ) {
        float r = 0.0f;
#pragma unroll
        for (int w = 0; w < NWARP; w++) r += sm.red[w][tid];
        out[samp * NQ + tid] = r;
    }
}

extern "C" void kernel_launch(void* const* d_in, const int* in_sizes, int n_in,
                              void* d_out, int out_size)
{
    const float* x = (const float*)d_in[0];
    const float* w = (const float*)d_in[1];
    if (n_in >= 2 && in_sizes[0] == 3 * NQ && in_sizes[1] != 3 * NQ) {
        // defensive: inputs arrived as (weights, x)
        const float* tmp = x; x = w; w = tmp;
    }
    const int batch = out_size / NQ;

    cudaFuncSetAttribute(qsim_kernel,
                         cudaFuncAttributeMaxDynamicSharedMemorySize,
                         NSTATE * (int)sizeof(float2));

    qsim_kernel<<<batch, THREADS, NSTATE * sizeof(float2)>>>(x, w, (float*)d_out);
}